// round 2
// baseline (speedup 1.0000x reference)
#include <cuda_runtime.h>
#include <cstdint>

#define NTH   512
#define KSEL  100
#define NBINS 4096
#define CAP   1024

struct SMem {
    unsigned long long cand[CAP];     // 8192 B (also aliased as psum[512])
    unsigned hist[NBINS];             // 16384 B
    float s_data[KSEL * 16];
    float s_box[KSEL * 4];
    float s_val[KSEL];
    float s_bel[KSEL];
    float s_area[KSEL];
    int   s_keep[KSEL];
    int   s_vld[KSEL];
    int   s_nk[KSEL];
    unsigned sup[KSEL][4];
    unsigned wball[4];
    float    wmax[4];
    int      wmaxi[4];
    unsigned vkball[4];
    unsigned km[4];
    int s_T;
    unsigned s_cnt;
    int s_anyVK;
    int s_bi;
};

__device__ __forceinline__ unsigned fkey(float f) {
    unsigned u = __float_as_uint(f);
    return (u & 0x80000000u) ? ~u : (u | 0x80000000u);
}

__global__ __launch_bounds__(NTH) void pp_kernel(
    const float* __restrict__ blk_logit,
    const float* __restrict__ lin_logit,
    const float* __restrict__ chr_logit,
    const float* __restrict__ blk_raw,
    const float* __restrict__ lin_raw,
    const float* __restrict__ chr_raw,
    const float* __restrict__ tsz,
    float* __restrict__ out,
    int B, int NB, int NL, int NC)
{
    const int b   = blockIdx.x;
    const int lvl = blockIdx.y;
    const int tid = threadIdx.x;
    const int wid = tid >> 5;
    const int lane = tid & 31;

    int N, PN = 0, ef = 1;
    const float *logit, *raw, *praw = nullptr;
    bool bez = false;
    if (lvl == 0)      { N = NB; logit = blk_logit; raw = blk_raw; }
    else if (lvl == 1) { N = NL; logit = lin_logit; raw = lin_raw; praw = blk_raw; PN = NB; ef = 4; }
    else               { N = NC; logit = chr_logit; raw = chr_raw; praw = lin_raw; PN = NL; ef = 1; bez = true; }

    __shared__ SMem sm;

    for (int i = tid; i < NBINS; i += NTH) sm.hist[i] = 0;
    if (tid == 0) sm.s_cnt = 0;
    __syncthreads();

    // ---- Pass 1: histogram of top 12 key bits (float4 vectorized) ----
    const float4* lp4 = (const float4*)(logit + (size_t)b * N);
    const int n4 = N >> 2;
    for (int i = tid; i < n4; i += NTH) {
        float4 v = lp4[i];
        atomicAdd(&sm.hist[fkey(v.x) >> 20], 1u);
        atomicAdd(&sm.hist[fkey(v.y) >> 20], 1u);
        atomicAdd(&sm.hist[fkey(v.z) >> 20], 1u);
        atomicAdd(&sm.hist[fkey(v.w) >> 20], 1u);
    }
    __syncthreads();

    // ---- Per-thread chunk sums (8 bins each), aliased onto cand area ----
    unsigned* psum = (unsigned*)sm.cand;
    {
        unsigned s = 0;
        int base = tid * (NBINS / NTH);
        #pragma unroll
        for (int j = 0; j < NBINS / NTH; ++j) s += sm.hist[base + j];
        psum[tid] = s;
    }
    __syncthreads();

    // ---- Warp 0: find largest bin T with count(bins >= T) >= KSEL ----
    if (tid < 32) {
        const unsigned FULL = 0xffffffffu;
        unsigned carry = 0;
        for (int g = 15; g >= 0; --g) {
            unsigned v = psum[g * 32 + lane];
            unsigned s = v;
            #pragma unroll
            for (int off = 1; off < 32; off <<= 1) {
                unsigned n = __shfl_down_sync(FULL, s, off);
                if (lane + off < 32) s += n;
            }
            unsigned gsum = __shfl_sync(FULL, s, 0);
            if (carry + gsum >= (unsigned)KSEL) {
                unsigned ball = __ballot_sync(FULL, carry + s >= (unsigned)KSEL);
                int hi = 31 - __clz(ball);
                unsigned s_hi = __shfl_sync(FULL, s, hi);
                unsigned v_hi = __shfl_sync(FULL, v, hi);
                if (lane == 0) {
                    unsigned above = carry + s_hi - v_hi;
                    int C = g * 32 + hi;
                    int T = C * 8;
                    for (int w = 7; w >= 0; --w) {
                        above += sm.hist[C * 8 + w];
                        if (above >= (unsigned)KSEL) { T = C * 8 + w; break; }
                    }
                    sm.s_T = T;
                }
                break;
            }
            carry += gsum;
        }
    }
    __syncthreads();
    const unsigned T = (unsigned)sm.s_T;

    // ---- Collect candidates (recompute keys; logits are L1-hot) ----
    for (int i = tid; i < n4; i += NTH) {
        float4 v = lp4[i];
        unsigned kk[4] = { fkey(v.x), fkey(v.y), fkey(v.z), fkey(v.w) };
        #pragma unroll
        for (int q = 0; q < 4; ++q) {
            if ((kk[q] >> 20) >= T) {
                unsigned pos = atomicAdd(&sm.s_cnt, 1u);
                if (pos < CAP)
                    sm.cand[pos] = ((unsigned long long)kk[q] << 32) | (unsigned)(~(4 * i + q));
            }
        }
    }
    __syncthreads();
    int cnt = (int)sm.s_cnt; if (cnt > CAP) cnt = CAP;
    int P = 128; while (P < cnt) P <<= 1;
    for (int i = tid; i < P; i += NTH) if (i >= cnt) sm.cand[i] = 0ULL;
    __syncthreads();

    // ---- Bitonic sort descending (composite = (key, ~idx): stable) ----
    for (int k = 2; k <= P; k <<= 1) {
        for (int j = k >> 1; j > 0; j >>= 1) {
            for (int i = tid; i < P; i += NTH) {
                int ixj = i ^ j;
                if (ixj > i) {
                    unsigned long long a = sm.cand[i], c2 = sm.cand[ixj];
                    bool desc = ((i & k) == 0);
                    if (desc ? (a < c2) : (a > c2)) { sm.cand[i] = c2; sm.cand[ixj] = a; }
                }
            }
            __syncthreads();
        }
    }

    const float ih = tsz[2 * b + 0];
    const float iw = tsz[2 * b + 1];

    // ---- Per-row decode ----
    if (tid < KSEL) {
        unsigned long long e = sm.cand[tid];
        unsigned key = (unsigned)(e >> 32);
        int idx = (int)(~((unsigned)e));
        unsigned u = (key & 0x80000000u) ? (key ^ 0x80000000u) : ~key;
        float lg = __uint_as_float(u);
        float prob = 1.0f / (1.0f + expf(-lg));
        sm.s_val[tid] = prob;
        sm.s_keep[tid] = prob > 0.1f;

        float bx0, bx1, bx2, bx3;
        if (!bez) {
            const float* rp = raw + ((size_t)b * N + idx) * 4;
            float cx = rp[0], cy = rp[1], bw = rp[2], bh = rp[3];
            bx0 = (cx - 0.5f * bw) * iw;
            bx1 = (cy - 0.5f * bh) * ih;
            bx2 = (cx + 0.5f * bw) * iw;
            bx3 = (cy + 0.5f * bh) * ih;
            if (lvl == 0) {
                bx0 = fminf(fmaxf(bx0, 0.f), iw);
                bx1 = fminf(fmaxf(bx1, 0.f), ih);
                bx2 = fminf(fmaxf(bx2, 0.f), iw);
                bx3 = fminf(fmaxf(bx3, 0.f), ih);
            }
            sm.s_data[tid * 16 + 0] = bx0; sm.s_data[tid * 16 + 1] = bx1;
            sm.s_data[tid * 16 + 2] = bx2; sm.s_data[tid * 16 + 3] = bx3;
        } else {
            const float* rp = raw + ((size_t)b * N + idx) * 16;
            float cpt[16];
            #pragma unroll
            for (int q = 0; q < 8; ++q) {
                cpt[2 * q + 0] = rp[2 * q + 0] * ih;
                cpt[2 * q + 1] = rp[2 * q + 1] * iw;
            }
            #pragma unroll
            for (int q = 0; q < 16; ++q) sm.s_data[tid * 16 + q] = cpt[q];
            float mn0 = 1e30f, mn1 = 1e30f, mx0 = -1e30f, mx1 = -1e30f;
            #pragma unroll
            for (int s2 = 0; s2 < 10; ++s2) {
                float t  = (float)s2 / 9.0f;
                float ti = 1.0f - t;
                float b0 = ti * ti * ti, b1 = 3.f * t * ti * ti;
                float b2 = 3.f * t * t * ti, b3 = t * t * t;
                float p0 = b0 * cpt[0] + b1 * cpt[2] + b2 * cpt[4]  + b3 * cpt[6];
                float p1 = b0 * cpt[1] + b1 * cpt[3] + b2 * cpt[5]  + b3 * cpt[7];
                float q0 = b0 * cpt[8] + b1 * cpt[10] + b2 * cpt[12] + b3 * cpt[14];
                float q1 = b0 * cpt[9] + b1 * cpt[11] + b2 * cpt[13] + b3 * cpt[15];
                mn0 = fminf(mn0, fminf(p0, q0));
                mn1 = fminf(mn1, fminf(p1, q1));
                mx0 = fmaxf(mx0, fmaxf(p0, q0));
                mx1 = fmaxf(mx1, fmaxf(p1, q1));
            }
            bx0 = mn0; bx1 = mn1; bx2 = mx0; bx3 = mx1;
        }
        sm.s_box[tid * 4 + 0] = bx0; sm.s_box[tid * 4 + 1] = bx1;
        sm.s_box[tid * 4 + 2] = bx2; sm.s_box[tid * 4 + 3] = bx3;
        float area = (bx2 - bx0) * (bx3 - bx1);
        sm.s_area[tid] = area;

        if (lvl > 0) {
            const float* pr = praw + ((size_t)b * PN + idx / ef) * 4;
            float pcx = pr[0], pcy = pr[1], pw = pr[2], ph = pr[3];
            float px0 = (pcx - 0.5f * pw) * iw, py0 = (pcy - 0.5f * ph) * ih;
            float px1 = (pcx + 0.5f * pw) * iw, py1 = (pcy + 0.5f * ph) * ih;
            float ix1 = fmaxf(bx0, px0), iy1 = fmaxf(bx1, py0);
            float ix2 = fminf(bx2, px1), iy2 = fminf(bx3, py1);
            float inter = fmaxf(ix2 - ix1, 0.f) * fmaxf(iy2 - iy1, 0.f);
            float belong = inter / (area + 1e-6f);
            sm.s_bel[tid] = belong;
            sm.s_vld[tid] = belong > 0.6f;
        }
    }
    __syncthreads();

    // ---- keep.any() fallback via ballots ----
    if (tid < 128) {
        bool kp = (tid < KSEL) && (sm.s_keep[tid] != 0);
        unsigned bal = __ballot_sync(0xffffffffu, kp);
        if (lane == 0) sm.wball[wid] = bal;
    }
    __syncthreads();
    if (tid == 0) {
        unsigned any = sm.wball[0] | sm.wball[1] | sm.wball[2] | sm.wball[3];
        if (!any) sm.s_keep[0] = 1;
    }
    __syncthreads();

    // ---- belong-valid fallback (argmax) via warp reduce ----
    if (lvl > 0) {
        if (tid < 128) {
            bool valid = tid < KSEL;
            bool kp = valid && (sm.s_keep[tid] != 0);
            float v = kp ? sm.s_bel[tid] : -3.0e38f;
            int   ix = tid;
            #pragma unroll
            for (int off = 16; off > 0; off >>= 1) {
                float ov = __shfl_down_sync(0xffffffffu, v, off);
                int   oi = __shfl_down_sync(0xffffffffu, ix, off);
                if (ov > v || (ov == v && oi < ix)) { v = ov; ix = oi; }
            }
            unsigned vk = __ballot_sync(0xffffffffu, kp && (sm.s_vld[tid] != 0));
            if (lane == 0) { sm.wmax[wid] = v; sm.wmaxi[wid] = ix; sm.vkball[wid] = vk; }
        }
        __syncthreads();
        if (tid == 0) {
            float bv = sm.wmax[0]; int bidx = sm.wmaxi[0];
            #pragma unroll
            for (int w = 1; w < 4; ++w)
                if (sm.wmax[w] > bv) { bv = sm.wmax[w]; bidx = sm.wmaxi[w]; }
            sm.s_anyVK = (sm.vkball[0] | sm.vkball[1] | sm.vkball[2] | sm.vkball[3]) != 0;
            sm.s_bi = bidx;
        }
        __syncthreads();
    }
    if (tid < KSEL) {
        bool kp = sm.s_keep[tid] != 0;
        int m;
        if (lvl > 0) m = sm.s_anyVK ? (kp && sm.s_vld[tid]) : (kp && (tid == sm.s_bi));
        else m = kp;
        sm.s_nk[tid] = m;
    }

    // ---- NMS: parallel suppression matrix ----
    __syncthreads();
    if (tid < KSEL) {
        float ax0 = sm.s_box[tid * 4 + 0], ay0 = sm.s_box[tid * 4 + 1];
        float ax1 = sm.s_box[tid * 4 + 2], ay1 = sm.s_box[tid * 4 + 3];
        float aa = sm.s_area[tid];
        unsigned m0 = 0, m1 = 0, m2 = 0, m3 = 0;
        for (int j = tid + 1; j < KSEL; ++j) {
            float bx0 = sm.s_box[j * 4 + 0], by0 = sm.s_box[j * 4 + 1];
            float bx1 = sm.s_box[j * 4 + 2], by1 = sm.s_box[j * 4 + 3];
            float ix0 = fmaxf(ax0, bx0), iy0 = fmaxf(ay0, by0);
            float ix1 = fminf(ax1, bx1), iy1 = fminf(ay1, by1);
            float inter = fmaxf(ix1 - ix0, 0.f) * fmaxf(iy1 - iy0, 0.f);
            float iou = inter / (aa + sm.s_area[j] - inter);
            if (iou > 0.1f) {
                unsigned bit = 1u << (j & 31);
                int w = j >> 5;
                if (w == 0) m0 |= bit; else if (w == 1) m1 |= bit;
                else if (w == 2) m2 |= bit; else m3 |= bit;
            }
        }
        sm.sup[tid][0] = m0; sm.sup[tid][1] = m1;
        sm.sup[tid][2] = m2; sm.sup[tid][3] = m3;
    }
    if (tid < 128) {
        unsigned bal = __ballot_sync(0xffffffffu, (tid < KSEL) && sm.s_nk[tid]);
        if (lane == 0) sm.km[wid] = bal;
    }
    __syncthreads();

    // ---- Single-thread bitmask greedy scan (no barriers) ----
    if (tid == 0) {
        unsigned k0 = sm.km[0], k1 = sm.km[1], k2 = sm.km[2], k3 = sm.km[3];
        for (int i = 0; i < KSEL; ++i) {
            unsigned word = (i < 32) ? k0 : (i < 64) ? k1 : (i < 96) ? k2 : k3;
            if ((word >> (i & 31)) & 1u) {
                k0 &= ~sm.sup[i][0];
                k1 &= ~sm.sup[i][1];
                k2 &= ~sm.sup[i][2];
                k3 &= ~sm.sup[i][3];
            }
        }
        sm.km[0] = k0; sm.km[1] = k1; sm.km[2] = k2; sm.km[3] = k3;
    }
    __syncthreads();

    // ---- Write outputs ----
    size_t nbd = (size_t)B * 400;
    size_t nsc = (size_t)B * 100;
    size_t oD, oS, oK;
    if (lvl == 0)      { oD = 0; oS = nbd; oK = nbd + nsc; }
    else if (lvl == 1) { size_t base = nbd + 2 * nsc; oD = base; oS = base + nbd; oK = oS + nsc; }
    else               { size_t base = 2 * (nbd + 2 * nsc); oD = base; oS = base + (size_t)B * 1600; oK = oS + nsc; }

    if (tid < KSEL) {
        bool nk = (sm.km[tid >> 5] >> (tid & 31)) & 1u;
        out[oS + (size_t)b * 100 + tid] = nk ? sm.s_val[tid] : 0.f;
        out[oK + (size_t)b * 100 + tid] = nk ? 1.f : 0.f;
        int D = bez ? 16 : 4;
        float* dp = out + oD + ((size_t)b * 100 + tid) * D;
        for (int d2 = 0; d2 < D; ++d2) dp[d2] = nk ? sm.s_data[tid * 16 + d2] : 0.f;
    }
}

extern "C" void kernel_launch(void* const* d_in, const int* in_sizes, int n_in,
                              void* d_out, int out_size) {
    const float* blk_logit = (const float*)d_in[0];
    const float* lin_logit = (const float*)d_in[1];
    const float* chr_logit = (const float*)d_in[2];
    const float* blk_raw   = (const float*)d_in[3];
    const float* lin_raw   = (const float*)d_in[4];
    const float* chr_raw   = (const float*)d_in[5];
    const float* tsz       = (const float*)d_in[6];
    float* out = (float*)d_out;

    int B  = in_sizes[6] / 2;
    int NB = in_sizes[0] / B;
    int NL = in_sizes[1] / B;
    int NC = in_sizes[2] / B;

    dim3 grid(B, 3);
    pp_kernel<<<grid, NTH>>>(blk_logit, lin_logit, chr_logit,
                             blk_raw, lin_raw, chr_raw, tsz, out,
                             B, NB, NL, NC);
}